// round 12
// baseline (speedup 1.0000x reference)
#include <cuda_runtime.h>
#include <cstdint>

// ---------------- problem constants ----------------
#define N_B    32
#define C_IN   256
#define L_LEN  4096
#define C_OUT  256
#define KW     9
#define GROUPS 4
#define CPG    64
#define OPG    64
#define C_DIM  128
#define PAD    4

#define L_TILE 256
#define NTHR   256                          // 8 warps; warp tile = 32 l x 64 oc
#define XF_STRIDE 264                       // fp32 staging stride (words, 16B-aligned rows)
#define XH_STRIDE 264                       // fp16x2 rows; %32==8 -> mainloop conflict-free
#define EP_STRIDE 260                       // epilogue staging stride

// smem layout (bytes)
#define XF_SLOT_B (16 * XF_STRIDE * 4)      // 16,896 B per fp32 x chunk slot
#define B_SLOT_B  18432                     // 9 taps x 512 fp16x2 words per chunk
#define XH_B      (8 * XH_STRIDE * 4)       // 8,448 B packed A buffer
#define SM_XF     0                         // 3 x 16,896 = 50,688
#define SM_XH     (3 * XF_SLOT_B)           // 50,688 .. 59,136
#define SM_B      (SM_XH + XH_B)            // 2 x 18,432 = 36,864
#define SM_CTX    (SM_B + 2 * B_SLOT_B)     // 96,000
#define SM_TOTAL  (SM_CTX + 256)            // 96,256 B (x2 CTA/SM = 192,512)
// epilogue aliases [0, 66,560) -- dead after final barrier; ctx untouched

// ---------------- device scratch ----------------
__device__ float g_ctx[N_B * C_OUT];
// B tiles: per g: [t=4][k=9] blocks of 512 fp16x2 words, m16n8k16 frag order
__device__ unsigned int g_wt[GROUPS * 4 * KW * 512];

__device__ __forceinline__ uint32_t smem_u32(const void* p) {
    uint32_t a;
    asm("{ .reg .u64 t; cvta.to.shared.u64 t, %1; cvt.u32.u64 %0, t; }" : "=r"(a) : "l"(p));
    return a;
}
__device__ __forceinline__ uint32_t packh2(float hi, float lo) {
    uint32_t r;
    asm("cvt.rn.f16x2.f32 %0, %1, %2;" : "=r"(r) : "f"(hi), "f"(lo));
    return r;
}
__device__ __forceinline__ void cp16(uint32_t dst, const void* src) {
    asm volatile("cp.async.cg.shared.global [%0], [%1], 16;" :: "r"(dst), "l"(src));
}
__device__ __forceinline__ void cp16z(uint32_t dst, const void* src, uint32_t src_size) {
    asm volatile("cp.async.cg.shared.global [%0], [%1], 16, %2;"
                 :: "r"(dst), "l"(src), "r"(src_size));
}
#define CP_COMMIT() asm volatile("cp.async.commit_group;" ::: "memory")
#define CP_WAIT1()  asm volatile("cp.async.wait_group 1;" ::: "memory")

__device__ __forceinline__ void mma_f16(float* d, const uint32_t* a, uint32_t b0, uint32_t b1) {
    asm("mma.sync.aligned.m16n8k16.row.col.f32.f16.f16.f32 "
        "{%0,%1,%2,%3}, {%4,%5,%6,%7}, {%8,%9}, {%0,%1,%2,%3};"
        : "+f"(d[0]), "+f"(d[1]), "+f"(d[2]), "+f"(d[3])
        : "r"(a[0]), "r"(a[1]), "r"(a[2]), "r"(a[3]), "r"(b0), "r"(b1));
}

// ---------------------------------------------------------------------------
// prep_kernel: blocks [0,36) -> fp16x2 B fragment tiles; [36,164) -> ctx GEMM.
// ---------------------------------------------------------------------------
__global__ void prep_kernel(const float* __restrict__ w,
                            const float* __restrict__ c,
                            const float* __restrict__ cw) {
    int bx = blockIdx.x, tid = threadIdx.x;
    if (bx < GROUPS * KW) {
        int g = bx / KW, k = bx - g * KW;
        for (int idx = tid; idx < 2048; idx += 256) {
            int r    = idx & 1;
            int qlo  = (idx >> 1) & 1;
            int lane = (idx >> 2) & 31;
            int qq   = (idx >> 7) & 3;
            int t    = idx >> 9;
            int oc   = 8 * (2 * qq + qlo) + (lane >> 2);
            int ic   = 16 * t + 2 * (lane & 3) + 8 * r;
            const float* wr = w + (size_t)(g * OPG + oc) * (CPG * KW) + k;
            float lo = wr[ic * KW];
            float hi = wr[(ic + 1) * KW];
            g_wt[(size_t)g * 18432 + (t * KW + k) * 512 +
                 (qq * 128 + lane * 4 + qlo * 2 + r)] = packh2(hi, lo);
        }
    } else {
        int o  = (bx - GROUPS * KW) * 64 + (tid >> 2);   // 0..8191
        int n  = o >> 8, oc = o & 255;
        const float* cr = c  + (size_t)n  * C_DIM + (tid & 3) * 32;
        const float* wr = cw + (size_t)oc * C_DIM + (tid & 3) * 32;
        float s = 0.f;
#pragma unroll 8
        for (int d = 0; d < 32; d++) s += cr[d] * wr[d];
        s += __shfl_down_sync(0xFFFFFFFFu, s, 2);
        s += __shfl_down_sync(0xFFFFFFFFu, s, 1);
        if ((tid & 3) == 0) g_ctx[o] = s;
    }
}

// ---------------------------------------------------------------------------
// conv_kernel: grouped conv as implicit GEMM (fp16 m16n8k16, fp32 accum).
// Block (lt, g, n): 256 l x 64 oc, 8 warps; warp = 32 l x 64 oc.
// Outer t = 4 ic-chunks of 16. xf 3-slot ring (cp.async, lookahead 2);
// B 2-slot ring (cp.async, lookahead 1). ONE barrier per chunk.
// Per-warp halo conversion fp32 -> packed fp16x2 (xh), warp-local.
// ---------------------------------------------------------------------------
__global__ void __launch_bounds__(NTHR, 2)
conv_kernel(const float* __restrict__ x, const float* __restrict__ bias,
            float* __restrict__ out) {
    extern __shared__ char smem[];
    const uint32_t sb = smem_u32(smem);

    const int tid = threadIdx.x;
    const int wid = tid >> 5, lane = tid & 31;
    const int lt = blockIdx.x, g = blockIdx.y, n = blockIdx.z;
    const int l0 = lt * L_TILE;

    const float* xb = x + ((size_t)(n * C_IN + g * CPG)) * L_LEN + (l0 - PAD);
    const char*  bw = (const char*)(g_wt + (size_t)g * 18432);

    // --- issue helpers ---
    auto issue_x = [&](int t) {                    // x chunk t (16 ic rows) -> slot t%3
        uint32_t base = sb + SM_XF + (t % 3) * XF_SLOT_B;
        const float* src0 = xb + (size_t)(16 * t) * L_LEN;
#pragma unroll
        for (int it = 0; it < 5; it++) {           // 16 rows x 66 quads = 1056
            int i = tid + it * NTHR;
            if (i < 1056) {
                int row = i / 66, c = i - row * 66;
                int gl = l0 - PAD + 4 * c;
                uint32_t sz = (gl >= 0 && gl <= L_LEN - 4) ? 16u : 0u;
                cp16z(base + (row * XF_STRIDE + 4 * c) * 4,
                      src0 + (size_t)row * L_LEN + 4 * c, sz);
            }
        }
    };
    auto issue_b = [&](int t) {                    // B chunk t -> slot t%2
        uint32_t base = sb + SM_B + (t & 1) * B_SLOT_B;
        const char* src = bw + (size_t)t * B_SLOT_B;
#pragma unroll
        for (int it = 0; it < 5; it++) {           // 18,432 B = 1152 chunks
            int i = tid + it * NTHR;
            if (i < 1152) cp16(base + i * 16, src + (size_t)i * 16);
        }
    };

    // ---- prologue commits: x0, B0, x1  (queue: [x0, B0, x1]) ----
    issue_x(0); CP_COMMIT();
    issue_b(0); CP_COMMIT();
    issue_x(1); CP_COMMIT();

    if (tid < OPG) {
        int goc = g * OPG + tid;
        ((float*)(smem + SM_CTX))[tid] = g_ctx[n * C_OUT + goc] + bias[goc];
    }

    // ---- accumulators ----
    float d[2][8][4];
#pragma unroll
    for (int mi = 0; mi < 2; mi++)
#pragma unroll
        for (int f = 0; f < 8; f++)
#pragma unroll
            for (int r = 0; r < 4; r++) d[mi][f][r] = 0.f;

    const int ml  = wid * 32;
    const int gid = lane >> 2;     // l offset within fragment (0..7)
    const int tig = lane & 3;      // ic-pair selector

#pragma unroll 1
    for (int t = 0; t < 4; t++) {
        // wait x(t), B(t): at most 1 younger group (x(t+1)) may stay pending
        CP_WAIT1();
        __syncthreads();           // data visibility + ring/xh safety (only bar/chunk)

        // ---- per-warp halo convert: pairs 0..7, cols [ml, ml+40) ----
        {
            const float* xsf = (const float*)(smem + SM_XF + (t % 3) * XF_SLOT_B);
            uint32_t* xh = (uint32_t*)(smem + SM_XH);
#pragma unroll
            for (int j = 0; j < 10; j++) {         // 8 pairs x 40 cols = 320 / 32 lanes
                int i = lane + 32 * j;
                int p = i / 40, c = ml + (i - 40 * p);
                float lo = xsf[(2 * p)     * XF_STRIDE + c];
                float hi = xsf[(2 * p + 1) * XF_STRIDE + c];
                xh[p * XH_STRIDE + c] = packh2(hi, lo);
            }
        }

        // issue next chunks (slots distinct from any live data)
        if (t + 1 < 4) issue_b(t + 1);
        CP_COMMIT();
        if (t + 2 < 4) issue_x(t + 2);
        CP_COMMIT();

        const uint32_t* xh  = (const uint32_t*)(smem + SM_XH);
        const char*    bbsl = smem + SM_B + (t & 1) * B_SLOT_B;
        const uint32_t* xr0 = xh + tig * XH_STRIDE + (ml + gid);
        const uint32_t* xr4 = xr0 + 4 * XH_STRIDE;

#pragma unroll
        for (int k = 0; k < KW; k++) {
            // A fragments: 8 conflict-free LDS.32 (pre-packed fp16x2)
            uint32_t a[2][4];
#pragma unroll
            for (int mi = 0; mi < 2; mi++) {
                a[mi][0] = xr0[k + 16 * mi];
                a[mi][1] = xr0[k + 16 * mi + 8];
                a[mi][2] = xr4[k + 16 * mi];
                a[mi][3] = xr4[k + 16 * mi + 8];
            }
            // B fragments: 4 conflict-free LDS.128
            uint4 bq[4];
            {
                const uint4* bsrc = (const uint4*)(bbsl + k * 2048) + lane;
#pragma unroll
                for (int qq = 0; qq < 4; qq++) bq[qq] = bsrc[qq * 32];
            }
#pragma unroll
            for (int mi = 0; mi < 2; mi++) {
#pragma unroll
                for (int qq = 0; qq < 4; qq++) {
                    mma_f16(d[mi][2 * qq],     a[mi], bq[qq].x, bq[qq].y);
                    mma_f16(d[mi][2 * qq + 1], a[mi], bq[qq].z, bq[qq].w);
                }
            }
        }
    }
    __syncthreads();   // all compute done before epilogue clobbers buffers

    // ---- epilogue: stage through smem, coalesced float4 out ----
    float* ep = (float*)smem;             // [oc][l], stride EP_STRIDE
#pragma unroll
    for (int mi = 0; mi < 2; mi++) {
#pragma unroll
        for (int f = 0; f < 8; f++) {
            int l  = ml + 16 * mi + gid;
            int oc = 8 * f + 2 * tig;
            ep[oc * EP_STRIDE + l]           = d[mi][f][0];
            ep[(oc + 1) * EP_STRIDE + l]     = d[mi][f][1];
            ep[oc * EP_STRIDE + l + 8]       = d[mi][f][2];
            ep[(oc + 1) * EP_STRIDE + l + 8] = d[mi][f][3];
        }
    }
    __syncthreads();

    const float* sadd = (const float*)(smem + SM_CTX);
#pragma unroll
    for (int i = 0; i < 8; i++) {
        int oc  = wid * 8 + i;
        int goc = g * OPG + oc;
        float add = sadd[oc];
        const float4* src = (const float4*)(ep + oc * EP_STRIDE);
        float4* dst = (float4*)(out + ((size_t)(n * C_OUT + goc)) * L_LEN + l0);
#pragma unroll
        for (int it = 0; it < 2; it++) {
            float4 v = src[lane + it * 32];
            v.x += add; v.y += add; v.z += add; v.w += add;
            dst[lane + it * 32] = v;
        }
    }
}

// ---------------------------------------------------------------------------
extern "C" void kernel_launch(void* const* d_in, const int* in_sizes, int n_in,
                              void* d_out, int out_size) {
    const float* x    = (const float*)d_in[0];  // (32, 256, 4096)
    const float* c    = (const float*)d_in[1];  // (32, 128)
    const float* w    = (const float*)d_in[2];  // (256, 64, 9)
    const float* cw   = (const float*)d_in[3];  // (256, 128)
    const float* bias = (const float*)d_in[4];  // (256,)
    float* out = (float*)d_out;                 // (32, 256, 4096)

    cudaFuncSetAttribute(conv_kernel, cudaFuncAttributeMaxDynamicSharedMemorySize, SM_TOTAL);

    prep_kernel<<<GROUPS * KW + 128, 256>>>(w, c, cw);
    dim3 grid(L_LEN / L_TILE, GROUPS, N_B);     // (16, 4, 32)
    conv_kernel<<<grid, NTHR, SM_TOTAL>>>(x, bias, out);
}

// round 13
// speedup vs baseline: 1.0294x; 1.0294x over previous
#include <cuda_runtime.h>
#include <cstdint>

// ---------------- problem constants ----------------
#define N_B    32
#define C_IN   256
#define L_LEN  4096
#define C_OUT  256
#define KW     9
#define GROUPS 4
#define CPG    64
#define OPG    64
#define C_DIM  128
#define PAD    4

#define L_TILE 128
#define NTHR   128                          // 4 warps; warp tile = 32 l x 64 oc
#define XF_STRIDE 136                       // fp32 staging stride (words, 16B rows)
#define XH_STRIDE 136                       // fp16x2 rows; %32==8 -> A loads conflict-free
#define EP_STRIDE 132                       // epilogue staging stride

// smem layout (bytes)
#define XF_SLOT_B (16 * XF_STRIDE * 4)      // 8,704 B per fp32 x chunk slot
#define B_SLOT_B  18432                     // 9 taps x 512 fp16x2 words per chunk
#define XH_B      (8 * XH_STRIDE * 4)       // 4,352 B packed A buffer
#define SM_XF     0                         // 3 x 8,704 = 26,112
#define SM_XH     (3 * XF_SLOT_B)           // 26,112 .. 30,464
#define SM_B      (SM_XH + XH_B)            // 2 x 18,432 = 36,864
#define SM_CTX    (SM_B + 2 * B_SLOT_B)     // 67,328
#define SM_TOTAL  (SM_CTX + 256)            // 67,584 B (x3 CTA/SM = 202,752)
// epilogue aliases [0, 33,792) -- dead after final barrier; ctx untouched

// ---------------- device scratch ----------------
__device__ float g_ctx[N_B * C_OUT];
// B tiles: per g: [t=4][k=9] blocks of 512 fp16x2 words, m16n8k16 frag order
__device__ unsigned int g_wt[GROUPS * 4 * KW * 512];

__device__ __forceinline__ uint32_t smem_u32(const void* p) {
    uint32_t a;
    asm("{ .reg .u64 t; cvta.to.shared.u64 t, %1; cvt.u32.u64 %0, t; }" : "=r"(a) : "l"(p));
    return a;
}
__device__ __forceinline__ uint32_t packh2(float hi, float lo) {
    uint32_t r;
    asm("cvt.rn.f16x2.f32 %0, %1, %2;" : "=r"(r) : "f"(hi), "f"(lo));
    return r;
}
__device__ __forceinline__ void cp16(uint32_t dst, const void* src) {
    asm volatile("cp.async.cg.shared.global [%0], [%1], 16;" :: "r"(dst), "l"(src));
}
__device__ __forceinline__ void cp16z(uint32_t dst, const void* src, uint32_t src_size) {
    asm volatile("cp.async.cg.shared.global [%0], [%1], 16, %2;"
                 :: "r"(dst), "l"(src), "r"(src_size));
}
#define CP_COMMIT() asm volatile("cp.async.commit_group;" ::: "memory")
#define CP_WAIT1()  asm volatile("cp.async.wait_group 1;" ::: "memory")

__device__ __forceinline__ void mma_f16(float* d, const uint32_t* a, uint32_t b0, uint32_t b1) {
    asm("mma.sync.aligned.m16n8k16.row.col.f32.f16.f16.f32 "
        "{%0,%1,%2,%3}, {%4,%5,%6,%7}, {%8,%9}, {%0,%1,%2,%3};"
        : "+f"(d[0]), "+f"(d[1]), "+f"(d[2]), "+f"(d[3])
        : "r"(a[0]), "r"(a[1]), "r"(a[2]), "r"(a[3]), "r"(b0), "r"(b1));
}

// ---------------------------------------------------------------------------
// prep_kernel: blocks [0,36) -> fp16x2 B fragment tiles; [36,164) -> ctx GEMM.
// ---------------------------------------------------------------------------
__global__ void prep_kernel(const float* __restrict__ w,
                            const float* __restrict__ c,
                            const float* __restrict__ cw) {
    int bx = blockIdx.x, tid = threadIdx.x;
    if (bx < GROUPS * KW) {
        int g = bx / KW, k = bx - g * KW;
        for (int idx = tid; idx < 2048; idx += 256) {
            int r    = idx & 1;
            int qlo  = (idx >> 1) & 1;
            int lane = (idx >> 2) & 31;
            int qq   = (idx >> 7) & 3;
            int t    = idx >> 9;
            int oc   = 8 * (2 * qq + qlo) + (lane >> 2);
            int ic   = 16 * t + 2 * (lane & 3) + 8 * r;
            const float* wr = w + (size_t)(g * OPG + oc) * (CPG * KW) + k;
            float lo = wr[ic * KW];
            float hi = wr[(ic + 1) * KW];
            g_wt[(size_t)g * 18432 + (t * KW + k) * 512 +
                 (qq * 128 + lane * 4 + qlo * 2 + r)] = packh2(hi, lo);
        }
    } else {
        int o  = (bx - GROUPS * KW) * 64 + (tid >> 2);   // 0..8191
        int n  = o >> 8, oc = o & 255;
        const float* cr = c  + (size_t)n  * C_DIM + (tid & 3) * 32;
        const float* wr = cw + (size_t)oc * C_DIM + (tid & 3) * 32;
        float s = 0.f;
#pragma unroll 8
        for (int d = 0; d < 32; d++) s += cr[d] * wr[d];
        s += __shfl_down_sync(0xFFFFFFFFu, s, 2);
        s += __shfl_down_sync(0xFFFFFFFFu, s, 1);
        if ((tid & 3) == 0) g_ctx[o] = s;
    }
}

// ---------------------------------------------------------------------------
// conv_kernel: grouped conv as implicit GEMM (fp16 m16n8k16, fp32 accum).
// Block (lt, g, n): 128 l x 64 oc, 4 warps; warp = 32 l x 64 oc. 3 CTA/SM.
// launch_bounds(128,3) -> 170-reg budget funds an explicit k-pipeline:
// fragments for k+1 load during k's MMAs (parity-indexed, fully unrolled).
// ---------------------------------------------------------------------------
__global__ void __launch_bounds__(NTHR, 3)
conv_kernel(const float* __restrict__ x, const float* __restrict__ bias,
            float* __restrict__ out) {
    extern __shared__ char smem[];
    const uint32_t sb = smem_u32(smem);

    const int tid = threadIdx.x;
    const int wid = tid >> 5, lane = tid & 31;
    const int lt = blockIdx.x, g = blockIdx.y, n = blockIdx.z;
    const int l0 = lt * L_TILE;

    const float* xb = x + ((size_t)(n * C_IN + g * CPG)) * L_LEN + (l0 - PAD);
    const char*  bw = (const char*)(g_wt + (size_t)g * 18432);

    // --- issue helpers ---
    auto issue_x = [&](int t) {                    // x chunk t (16 ic rows) -> slot t%3
        uint32_t base = sb + SM_XF + (t % 3) * XF_SLOT_B;
        const float* src0 = xb + (size_t)(16 * t) * L_LEN;
#pragma unroll
        for (int it = 0; it < 5; it++) {           // 16 rows x 34 quads = 544
            int i = tid + it * NTHR;
            if (i < 544) {
                int row = i / 34, c = i - row * 34;
                int gl = l0 - PAD + 4 * c;
                uint32_t sz = (gl >= 0 && gl <= L_LEN - 4) ? 16u : 0u;
                cp16z(base + (row * XF_STRIDE + 4 * c) * 4,
                      src0 + (size_t)row * L_LEN + 4 * c, sz);
            }
        }
    };
    auto issue_b = [&](int t) {                    // B chunk t -> slot t%2
        uint32_t base = sb + SM_B + (t & 1) * B_SLOT_B;
        const char* src = bw + (size_t)t * B_SLOT_B;
#pragma unroll
        for (int it = 0; it < 9; it++) {           // 18,432 B = 1152 chunks
            int i = tid + it * NTHR;
            if (i < 1152) cp16(base + i * 16, src + (size_t)i * 16);
        }
    };

    // ---- prologue commits: x0, B0, x1  (queue: [x0, B0, x1]) ----
    issue_x(0); CP_COMMIT();
    issue_b(0); CP_COMMIT();
    issue_x(1); CP_COMMIT();

    if (tid < OPG) {
        int goc = g * OPG + tid;
        ((float*)(smem + SM_CTX))[tid] = g_ctx[n * C_OUT + goc] + bias[goc];
    }

    // ---- accumulators ----
    float d[2][8][4];
#pragma unroll
    for (int mi = 0; mi < 2; mi++)
#pragma unroll
        for (int f = 0; f < 8; f++)
#pragma unroll
            for (int r = 0; r < 4; r++) d[mi][f][r] = 0.f;

    const int ml  = wid * 32;
    const int gid = lane >> 2;     // l offset within fragment (0..7)
    const int tig = lane & 3;      // ic-pair selector

#pragma unroll 1
    for (int t = 0; t < 4; t++) {
        // wait x(t), B(t): at most 1 younger group (x(t+1)) pending
        CP_WAIT1();
        __syncthreads();           // data visibility + ring/xh safety

        // ---- per-warp halo convert: pairs 0..7, cols [ml, ml+40) ----
        {
            const float* xsf = (const float*)(smem + SM_XF + (t % 3) * XF_SLOT_B);
            uint32_t* xh = (uint32_t*)(smem + SM_XH);
#pragma unroll
            for (int j = 0; j < 10; j++) {         // 8 pairs x 40 cols / 32 lanes
                int i = lane + 32 * j;
                int p = i / 40, c = ml + (i - 40 * p);
                float lo = xsf[(2 * p)     * XF_STRIDE + c];
                float hi = xsf[(2 * p + 1) * XF_STRIDE + c];
                xh[p * XH_STRIDE + c] = packh2(hi, lo);
            }
        }
        __syncwarp();              // convert is warp-local; order STS -> LDS

        // issue next chunks
        if (t + 1 < 4) issue_b(t + 1);
        CP_COMMIT();
        if (t + 2 < 4) issue_x(t + 2);
        CP_COMMIT();

        const uint32_t* xh  = (const uint32_t*)(smem + SM_XH);
        const char*    bbsl = smem + SM_B + (t & 1) * B_SLOT_B;
        const uint32_t* xr0 = xh + tig * XH_STRIDE + (ml + gid);
        const uint32_t* xr4 = xr0 + 4 * XH_STRIDE;

        // ---- k-pipelined mainloop: frag double-buffer, parity indexed ----
        uint32_t a[2][2][4];
        uint4    b[2][4];
#define LOADF(buf, kk) do {                                                  \
            _Pragma("unroll")                                                \
            for (int mi = 0; mi < 2; mi++) {                                 \
                a[buf][mi][0] = xr0[(kk) + 16 * mi];                         \
                a[buf][mi][1] = xr0[(kk) + 16 * mi + 8];                     \
                a[buf][mi][2] = xr4[(kk) + 16 * mi];                         \
                a[buf][mi][3] = xr4[(kk) + 16 * mi + 8];                     \
            }                                                                \
            const uint4* bsrc = (const uint4*)(bbsl + (kk) * 2048) + lane;   \
            _Pragma("unroll")                                                \
            for (int qq = 0; qq < 4; qq++) b[buf][qq] = bsrc[qq * 32];       \
        } while (0)

        LOADF(0, 0);
#pragma unroll
        for (int k = 0; k < KW; k++) {
            const int cur = k & 1, nxt = cur ^ 1;
            if (k < KW - 1) LOADF(nxt, k + 1);
#pragma unroll
            for (int mi = 0; mi < 2; mi++) {
#pragma unroll
                for (int qq = 0; qq < 4; qq++) {
                    mma_f16(d[mi][2 * qq],     a[cur][mi], b[cur][qq].x, b[cur][qq].y);
                    mma_f16(d[mi][2 * qq + 1], a[cur][mi], b[cur][qq].z, b[cur][qq].w);
                }
            }
        }
#undef LOADF
    }
    __syncthreads();   // all compute done before epilogue clobbers buffers

    // ---- epilogue: stage through smem, coalesced float4 out ----
    float* ep = (float*)smem;             // [oc][l], stride EP_STRIDE
#pragma unroll
    for (int mi = 0; mi < 2; mi++) {
#pragma unroll
        for (int f = 0; f < 8; f++) {
            int l  = ml + 16 * mi + gid;
            int oc = 8 * f + 2 * tig;
            ep[oc * EP_STRIDE + l]           = d[mi][f][0];
            ep[(oc + 1) * EP_STRIDE + l]     = d[mi][f][1];
            ep[oc * EP_STRIDE + l + 8]       = d[mi][f][2];
            ep[(oc + 1) * EP_STRIDE + l + 8] = d[mi][f][3];
        }
    }
    __syncthreads();

    const float* sadd = (const float*)(smem + SM_CTX);
#pragma unroll
    for (int i = 0; i < 16; i++) {
        int oc  = wid * 16 + i;
        int goc = g * OPG + oc;
        float add = sadd[oc];
        const float4* src = (const float4*)(ep + oc * EP_STRIDE);
        float4* dst = (float4*)(out + ((size_t)(n * C_OUT + goc)) * L_LEN + l0);
        float4 v = src[lane];
        v.x += add; v.y += add; v.z += add; v.w += add;
        dst[lane] = v;
    }
}

// ---------------------------------------------------------------------------
extern "C" void kernel_launch(void* const* d_in, const int* in_sizes, int n_in,
                              void* d_out, int out_size) {
    const float* x    = (const float*)d_in[0];  // (32, 256, 4096)
    const float* c    = (const float*)d_in[1];  // (32, 128)
    const float* w    = (const float*)d_in[2];  // (256, 64, 9)
    const float* cw   = (const float*)d_in[3];  // (256, 128)
    const float* bias = (const float*)d_in[4];  // (256,)
    float* out = (float*)d_out;                 // (32, 256, 4096)

    cudaFuncSetAttribute(conv_kernel, cudaFuncAttributeMaxDynamicSharedMemorySize, SM_TOTAL);

    prep_kernel<<<GROUPS * KW + 128, 256>>>(w, c, cw);
    dim3 grid(L_LEN / L_TILE, GROUPS, N_B);     // (32, 4, 32)
    conv_kernel<<<grid, NTHR, SM_TOTAL>>>(x, bias, out);
}